// round 5
// baseline (speedup 1.0000x reference)
#include <cuda_runtime.h>

// ---------------- problem constants ----------------
#define N_PTS 32768
#define TILE 2048
#define T_TILES (N_PTS / TILE)                        // 16
#define NPAIR_BLOCKS (T_TILES * (T_TILES + 1) / 2)    // 136
#define NEDGE_BLOCKS 12
#define NTOTAL_BLOCKS (NPAIR_BLOCKS + NEDGE_BLOCKS)   // 148 = one block per SM
#define THREADS 512
#define IB 8                                          // i-points per thread (512*8 = 4096? no: 512*8=4096)
// NOTE: 512 threads * IB must equal TILE => IB = TILE/THREADS = 4? Fix below.
#undef IB
#define IB (TILE / THREADS)                           // 4 ... too small; use 2 i-rows per thread pass
// We want NG=4 packed groups per thread => 8 i-points per thread => each thread
// covers 8 i's; with 512 threads that is 4096 i's, but TILE=2048. So each
// thread handles 8 i's and only 256 threads-worth of i-coverage is needed.
// Instead: keep 512 threads; thread handles IB=8 i's; i-coverage = 2048 needs
// 256 "i-threads" => split block: threads 0..255 take i-halves... Simpler:
// TILE_I (i-extent) = 4096? Can't: tiles must tile N. Final choice:
// i-tile = 2048 handled by 256 lanes x IB=8; the other 256 threads handle a
// SECOND j-tile? Too complex. Use THREADS=256, IB=8, TILE=2048, 136 blocks.
#undef THREADS
#define THREADS 256
#undef IB
#define IB 8
#define NG (IB / 2)                                   // 4 packed i-groups per thread
#define EDGE_THREADS 256
#define SCALE 3.5f
#define SCALE2 12.25f

// ---------------- device scratch (no allocs allowed) ----------------
__device__ double g_part[NPAIR_BLOCKS];  // per-block pair sums
__device__ double g_e1[NEDGE_BLOCKS];    // sum p*log(1+d2)
__device__ double g_e2[NEDGE_BLOCKS];    // sum p
__device__ double g_e3[NEDGE_BLOCKS];    // sum p*log(p)

typedef unsigned long long u64;

__device__ __forceinline__ float frcp(float x) {
    float r;
    asm("rcp.approx.ftz.f32 %0, %1;" : "=f"(r) : "f"(x));
    return r;
}
__device__ __forceinline__ u64 pack2(float lo, float hi) {
    u64 r;
    asm("mov.b64 %0, {%1, %2};" : "=l"(r) : "f"(lo), "f"(hi));
    return r;
}
__device__ __forceinline__ void unpack2(u64 v, float& lo, float& hi) {
    asm("mov.b64 {%0, %1}, %2;" : "=f"(lo), "=f"(hi) : "l"(v));
}
__device__ __forceinline__ u64 fma2(u64 a, u64 b, u64 c) {
    u64 d;
    asm("fma.rn.f32x2 %0, %1, %2, %3;" : "=l"(d) : "l"(a), "l"(b), "l"(c));
    return d;
}
__device__ __forceinline__ u64 add2(u64 a, u64 b) {
    u64 d;
    asm("add.rn.f32x2 %0, %1, %2;" : "=l"(d) : "l"(a), "l"(b));
    return d;
}
__device__ __forceinline__ u64 mul2(u64 a, u64 b) {
    u64 d;
    asm("mul.rn.f32x2 %0, %1, %2;" : "=l"(d) : "l"(a), "l"(b));
    return d;
}

// ---------------- fused kernel: 136 pair blocks + 12 edge blocks -------------
// Exactly 148 blocks = 1 per SM (occ=1 regime: all 148 SMs active, no waves,
// no multi-CTA spread). Pair blocks: full TILE x TILE square each (diagonal
// once, off-diagonal doubled by symmetry). Edge blocks run on the 12 SMs the
// pair grid leaves idle.
__global__ void __launch_bounds__(THREADS) k_fused(
        const float2* __restrict__ emb,
        const float* __restrict__ p,
        const int* __restrict__ heads,
        const int* __restrict__ tails, int E) {
    __shared__ __align__(16) u64 sx[TILE];
    __shared__ __align__(16) u64 sy[TILE];
    __shared__ __align__(16) u64 sz[TILE];

    int t = blockIdx.x;
    if (t < NPAIR_BLOCKS) {
        // ---- pair block ----
        int r = (int)((sqrtf(8.0f * (float)t + 1.0f) - 1.0f) * 0.5f);
        while ((r + 1) * (r + 2) / 2 <= t) r++;
        while (r * (r + 1) / 2 > t) r--;
        int c = t - r * (r + 1) / 2;
        int bi = c, bj = r;  // bi <= bj

        int jbase = bj * TILE;
        int ibase = bi * TILE;

        // cooperative j-tile load: scale + precompute, pre-broadcast packed
        for (int k = threadIdx.x; k < TILE; k += THREADS) {
            float2 e = emb[jbase + k];
            float x = e.x * SCALE;
            float y = e.y * SCALE;
            float sq = fmaf(x, x, y * y);
            sx[k] = pack2(x, x);
            sy[k] = pack2(y, y);
            sz[k] = pack2(1.0f + sq, 1.0f + sq);
        }
        __syncthreads();

        // per-thread i-points: IB=8 consecutive, packed 2 i's per register
        u64 m2[NG], n2[NG], s2[NG], acc2[NG];
        int i0 = ibase + threadIdx.x * IB;
#pragma unroll
        for (int g = 0; g < NG; g++) {
            float2 ea = emb[i0 + 2 * g];
            float2 eb = emb[i0 + 2 * g + 1];
            float xa = ea.x * SCALE, ya = ea.y * SCALE;
            float xb = eb.x * SCALE, yb = eb.y * SCALE;
            m2[g] = pack2(-2.0f * xa, -2.0f * xb);
            n2[g] = pack2(-2.0f * ya, -2.0f * yb);
            s2[g] = pack2(fmaf(xa, xa, ya * ya), fmaf(xb, xb, yb * yb));
            acc2[g] = pack2(0.0f, 0.0f);
        }

#pragma unroll 2
        for (int j = 0; j < TILE; j += 2) {
            ulonglong2 JX = *reinterpret_cast<const ulonglong2*>(&sx[j]);
            ulonglong2 JY = *reinterpret_cast<const ulonglong2*>(&sy[j]);
            ulonglong2 JZ = *reinterpret_cast<const ulonglong2*>(&sz[j]);
#pragma unroll
            for (int g = 0; g < NG; g++) {
                // denominators (1+d2) for (i0,i1) x (j, j+1)
                u64 d1 = fma2(m2[g], JX.x, fma2(n2[g], JY.x, add2(JZ.x, s2[g])));
                u64 d2 = fma2(m2[g], JX.y, fma2(n2[g], JY.y, add2(JZ.y, s2[g])));
                // 1/a + 1/b = (a+b) * rcp(a*b), packed per i-lane across j-pair
                u64 pr = mul2(d1, d2);
                u64 sm = add2(d1, d2);
                float plo, phi;
                unpack2(pr, plo, phi);
                u64 r2 = pack2(frcp(plo), frcp(phi));
                acc2[g] = fma2(sm, r2, acc2[g]);
            }
        }

        double dsum = 0.0;
#pragma unroll
        for (int g = 0; g < NG; g++) {
            float lo, hi;
            unpack2(acc2[g], lo, hi);
            dsum += (double)lo + (double)hi;
        }
        if (bi != bj) dsum *= 2.0;  // symmetry doubling

#pragma unroll
        for (int o = 16; o > 0; o >>= 1)
            dsum += __shfl_down_sync(0xffffffffu, dsum, o);

        double* sred = reinterpret_cast<double*>(sx);
        __syncthreads();
        if ((threadIdx.x & 31) == 0)
            sred[threadIdx.x >> 5] = dsum;
        __syncthreads();
        if (threadIdx.x == 0) {
            double v = 0.0;
#pragma unroll
            for (int w = 0; w < THREADS / 32; w++) v += sred[w];
            g_part[t] = v;
        }
    } else {
        // ---- edge block ----
        int b = t - NPAIR_BLOCKS;
        int tid = b * THREADS + threadIdx.x;
        int stride = NEDGE_BLOCKS * THREADS;
        float s1 = 0.0f, sp = 0.0f, se = 0.0f;
        for (int e = tid; e < E; e += stride) {
            int h = heads[e], tl = tails[e];
            float2 A = emb[h];
            float2 B = emb[tl];
            float dx = A.x - B.x;
            float dy = A.y - B.y;
            float d2 = SCALE2 * fmaf(dx, dx, dy * dy);
            float pe = p[e];
            s1 = fmaf(pe, __logf(1.0f + d2), s1);  // p * log(1+d2)
            sp += pe;
            se = fmaf(pe, __logf(pe), se);          // p * log(p)
        }
        double d1 = (double)s1, d2s = (double)sp, d3 = (double)se;
#pragma unroll
        for (int o = 16; o > 0; o >>= 1) {
            d1  += __shfl_down_sync(0xffffffffu, d1, o);
            d2s += __shfl_down_sync(0xffffffffu, d2s, o);
            d3  += __shfl_down_sync(0xffffffffu, d3, o);
        }
        double* sh1 = reinterpret_cast<double*>(sx);
        double* sh2 = sh1 + (THREADS / 32);
        double* sh3 = sh2 + (THREADS / 32);
        __syncthreads();
        if ((threadIdx.x & 31) == 0) {
            int w = threadIdx.x >> 5;
            sh1[w] = d1; sh2[w] = d2s; sh3[w] = d3;
        }
        __syncthreads();
        if (threadIdx.x == 0) {
            double v1 = 0.0, v2 = 0.0, v3 = 0.0;
#pragma unroll
            for (int w = 0; w < THREADS / 32; w++) {
                v1 += sh1[w]; v2 += sh2[w]; v3 += sh3[w];
            }
            g_e1[b] = v1; g_e2[b] = v2; g_e3[b] = v3;
        }
    }
}

// ---------------- final reduce + scalar assembly -----------------------------
__global__ void __launch_bounds__(256) k_final(float* out, int n) {
    double z = 0.0, e1 = 0.0, e2 = 0.0, e3 = 0.0;
    for (int i = threadIdx.x; i < NPAIR_BLOCKS; i += 256) z += g_part[i];
    if (threadIdx.x < NEDGE_BLOCKS) {
        e1 = g_e1[threadIdx.x];
        e2 = g_e2[threadIdx.x];
        e3 = g_e3[threadIdx.x];
    }
#pragma unroll
    for (int o = 16; o > 0; o >>= 1) {
        z  += __shfl_down_sync(0xffffffffu, z, o);
        e1 += __shfl_down_sync(0xffffffffu, e1, o);
        e2 += __shfl_down_sync(0xffffffffu, e2, o);
        e3 += __shfl_down_sync(0xffffffffu, e3, o);
    }
    __shared__ double sz_[8], s1_[8], s2_[8], s3_[8];
    if ((threadIdx.x & 31) == 0) {
        int w = threadIdx.x >> 5;
        sz_[w] = z; s1_[w] = e1; s2_[w] = e2; s3_[w] = e3;
    }
    __syncthreads();
    if (threadIdx.x == 0) {
        double Z = 0.0, t1 = 0.0, t2 = 0.0, t3 = 0.0;
#pragma unroll
        for (int w = 0; w < 8; w++) {
            Z += sz_[w]; t1 += s1_[w]; t2 += s2_[w]; t3 += s3_[w];
        }
        Z -= (double)n;  // remove diagonal (each contributes exactly 1)
        // loss = sum p*log(1+d2) + log(Z)*sum(p) + sum p*log(p)
        out[0] = (float)(t1 + log(Z) * t2 + t3);
    }
}

// ---------------- launch ------------------------------------------------------
extern "C" void kernel_launch(void* const* d_in, const int* in_sizes, int n_in,
                              void* d_out, int out_size) {
    const float2* emb   = (const float2*)d_in[0];
    const float*  p     = (const float*)d_in[1];
    const int*    heads = (const int*)d_in[2];
    const int*    tails = (const int*)d_in[3];
    int n = in_sizes[0] / 2;
    int E = in_sizes[1];

    k_fused<<<NTOTAL_BLOCKS, THREADS>>>(emb, p, heads, tails, E);
    k_final<<<1, 256>>>((float*)d_out, n);
}

// round 6
// speedup vs baseline: 1.9215x; 1.9215x over previous
#include <cuda_runtime.h>

// ---------------- problem constants ----------------
#define N_PTS 32768
#define TILE 2048                                     // i-extent per pair block
#define TILE_J 1024                                   // j-extent per pair block (square split in 2)
#define T_TILES (N_PTS / TILE)                        // 16
#define NSQUARES (T_TILES * (T_TILES + 1) / 2)        // 136 tile-squares
#define NPAIR_BLOCKS (NSQUARES * 2)                   // 272 (2 j-halves per square)
#define NEDGE_BLOCKS 24
#define NTOTAL_BLOCKS (NPAIR_BLOCKS + NEDGE_BLOCKS)   // 296 = 148 SMs x occ 2
#define THREADS 512
#define IB 4                                          // i-points per thread (512*4 = 2048)
#define NG (IB / 2)                                   // 2 packed i-groups per thread
#define SCALE 3.5f
#define SCALE2 12.25f

// ---------------- device scratch (no allocs allowed) ----------------
__device__ double g_part[NPAIR_BLOCKS];  // per-block pair sums
__device__ double g_e1[NEDGE_BLOCKS];    // sum p*log(1+d2)
__device__ double g_e2[NEDGE_BLOCKS];    // sum p
__device__ double g_e3[NEDGE_BLOCKS];    // sum p*log(p)

typedef unsigned long long u64;

__device__ __forceinline__ float frcp(float x) {
    float r;
    asm("rcp.approx.ftz.f32 %0, %1;" : "=f"(r) : "f"(x));
    return r;
}
__device__ __forceinline__ u64 pack2(float lo, float hi) {
    u64 r;
    asm("mov.b64 %0, {%1, %2};" : "=l"(r) : "f"(lo), "f"(hi));
    return r;
}
__device__ __forceinline__ void unpack2(u64 v, float& lo, float& hi) {
    asm("mov.b64 {%0, %1}, %2;" : "=f"(lo), "=f"(hi) : "l"(v));
}
__device__ __forceinline__ u64 fma2(u64 a, u64 b, u64 c) {
    u64 d;
    asm("fma.rn.f32x2 %0, %1, %2, %3;" : "=l"(d) : "l"(a), "l"(b), "l"(c));
    return d;
}
__device__ __forceinline__ u64 add2(u64 a, u64 b) {
    u64 d;
    asm("add.rn.f32x2 %0, %1, %2;" : "=l"(d) : "l"(a), "l"(b));
    return d;
}
__device__ __forceinline__ u64 mul2(u64 a, u64 b) {
    u64 d;
    asm("mul.rn.f32x2 %0, %1, %2;" : "=l"(d) : "l"(a), "l"(b));
    return d;
}

// ---------------- fused kernel: 272 pair blocks + 24 edge blocks -------------
// 296 blocks = 148 SMs x 2 resident CTAs (occ=2: no SM stranding, single
// wave). Each pair block: TILE x TILE_J rectangle (half of a tile-square;
// diagonal squares once, off-diagonal doubled by symmetry).
__global__ void __launch_bounds__(THREADS, 2) k_fused(
        const float2* __restrict__ emb,
        const float* __restrict__ p,
        const int* __restrict__ heads,
        const int* __restrict__ tails, int E) {
    __shared__ __align__(16) u64 sx[TILE_J];
    __shared__ __align__(16) u64 sy[TILE_J];
    __shared__ __align__(16) u64 sz[TILE_J];

    int q = blockIdx.x;
    if (q < NPAIR_BLOCKS) {
        // ---- pair block ----
        int t = q >> 1;       // square id
        int half = q & 1;     // j-half within the square
        // invert lower-triangular linear index: t = r*(r+1)/2 + c, c <= r
        int r = (int)((sqrtf(8.0f * (float)t + 1.0f) - 1.0f) * 0.5f);
        while ((r + 1) * (r + 2) / 2 <= t) r++;
        while (r * (r + 1) / 2 > t) r--;
        int c = t - r * (r + 1) / 2;
        int bi = c, bj = r;  // bi <= bj

        int jbase = bj * TILE + half * TILE_J;
        int ibase = bi * TILE;

        // cooperative j-tile load: scale + precompute, pre-broadcast packed
        for (int k = threadIdx.x; k < TILE_J; k += THREADS) {
            float2 e = emb[jbase + k];
            float x = e.x * SCALE;
            float y = e.y * SCALE;
            float sq = fmaf(x, x, y * y);
            sx[k] = pack2(x, x);
            sy[k] = pack2(y, y);
            sz[k] = pack2(1.0f + sq, 1.0f + sq);
        }
        __syncthreads();

        // per-thread i-points: IB=4 consecutive, packed 2 i's per register
        u64 m2[NG], n2[NG], s2[NG], acc2[NG];
        int i0 = ibase + threadIdx.x * IB;
#pragma unroll
        for (int g = 0; g < NG; g++) {
            float2 ea = emb[i0 + 2 * g];
            float2 eb = emb[i0 + 2 * g + 1];
            float xa = ea.x * SCALE, ya = ea.y * SCALE;
            float xb = eb.x * SCALE, yb = eb.y * SCALE;
            m2[g] = pack2(-2.0f * xa, -2.0f * xb);
            n2[g] = pack2(-2.0f * ya, -2.0f * yb);
            s2[g] = pack2(fmaf(xa, xa, ya * ya), fmaf(xb, xb, yb * yb));
            acc2[g] = pack2(0.0f, 0.0f);
        }

#pragma unroll 4
        for (int j = 0; j < TILE_J; j += 2) {
            ulonglong2 JX = *reinterpret_cast<const ulonglong2*>(&sx[j]);
            ulonglong2 JY = *reinterpret_cast<const ulonglong2*>(&sy[j]);
            ulonglong2 JZ = *reinterpret_cast<const ulonglong2*>(&sz[j]);
#pragma unroll
            for (int g = 0; g < NG; g++) {
                // denominators (1+d2) for (i0,i1) x (j, j+1)
                u64 d1 = fma2(m2[g], JX.x, fma2(n2[g], JY.x, add2(JZ.x, s2[g])));
                u64 d2 = fma2(m2[g], JX.y, fma2(n2[g], JY.y, add2(JZ.y, s2[g])));
                // 1/a + 1/b = (a+b) * rcp(a*b), packed per i-lane across j-pair
                u64 pr = mul2(d1, d2);
                u64 sm = add2(d1, d2);
                float plo, phi;
                unpack2(pr, plo, phi);
                u64 r2 = pack2(frcp(plo), frcp(phi));
                acc2[g] = fma2(sm, r2, acc2[g]);
            }
        }

        double dsum = 0.0;
#pragma unroll
        for (int g = 0; g < NG; g++) {
            float lo, hi;
            unpack2(acc2[g], lo, hi);
            dsum += (double)lo + (double)hi;
        }
        if (bi != bj) dsum *= 2.0;  // symmetry doubling

#pragma unroll
        for (int o = 16; o > 0; o >>= 1)
            dsum += __shfl_down_sync(0xffffffffu, dsum, o);

        double* sred = reinterpret_cast<double*>(sx);
        __syncthreads();
        if ((threadIdx.x & 31) == 0)
            sred[threadIdx.x >> 5] = dsum;
        __syncthreads();
        if (threadIdx.x == 0) {
            double v = 0.0;
#pragma unroll
            for (int w = 0; w < THREADS / 32; w++) v += sred[w];
            g_part[q] = v;
        }
    } else {
        // ---- edge block ----
        int b = q - NPAIR_BLOCKS;
        int tid = b * THREADS + threadIdx.x;
        int stride = NEDGE_BLOCKS * THREADS;
        float s1 = 0.0f, sp = 0.0f, se = 0.0f;
        for (int e = tid; e < E; e += stride) {
            int h = heads[e], tl = tails[e];
            float2 A = emb[h];
            float2 B = emb[tl];
            float dx = A.x - B.x;
            float dy = A.y - B.y;
            float d2 = SCALE2 * fmaf(dx, dx, dy * dy);
            float pe = p[e];
            s1 = fmaf(pe, __logf(1.0f + d2), s1);  // p * log(1+d2)
            sp += pe;
            se = fmaf(pe, __logf(pe), se);          // p * log(p)
        }
        double d1 = (double)s1, d2s = (double)sp, d3 = (double)se;
#pragma unroll
        for (int o = 16; o > 0; o >>= 1) {
            d1  += __shfl_down_sync(0xffffffffu, d1, o);
            d2s += __shfl_down_sync(0xffffffffu, d2s, o);
            d3  += __shfl_down_sync(0xffffffffu, d3, o);
        }
        double* sh1 = reinterpret_cast<double*>(sx);
        double* sh2 = sh1 + (THREADS / 32);
        double* sh3 = sh2 + (THREADS / 32);
        __syncthreads();
        if ((threadIdx.x & 31) == 0) {
            int w = threadIdx.x >> 5;
            sh1[w] = d1; sh2[w] = d2s; sh3[w] = d3;
        }
        __syncthreads();
        if (threadIdx.x == 0) {
            double v1 = 0.0, v2 = 0.0, v3 = 0.0;
#pragma unroll
            for (int w = 0; w < THREADS / 32; w++) {
                v1 += sh1[w]; v2 += sh2[w]; v3 += sh3[w];
            }
            g_e1[b] = v1; g_e2[b] = v2; g_e3[b] = v3;
        }
    }
}

// ---------------- final reduce + scalar assembly -----------------------------
__global__ void __launch_bounds__(256) k_final(float* out, int n) {
    double z = 0.0, e1 = 0.0, e2 = 0.0, e3 = 0.0;
    for (int i = threadIdx.x; i < NPAIR_BLOCKS; i += 256) z += g_part[i];
    if (threadIdx.x < NEDGE_BLOCKS) {
        e1 = g_e1[threadIdx.x];
        e2 = g_e2[threadIdx.x];
        e3 = g_e3[threadIdx.x];
    }
#pragma unroll
    for (int o = 16; o > 0; o >>= 1) {
        z  += __shfl_down_sync(0xffffffffu, z, o);
        e1 += __shfl_down_sync(0xffffffffu, e1, o);
        e2 += __shfl_down_sync(0xffffffffu, e2, o);
        e3 += __shfl_down_sync(0xffffffffu, e3, o);
    }
    __shared__ double sz_[8], s1_[8], s2_[8], s3_[8];
    if ((threadIdx.x & 31) == 0) {
        int w = threadIdx.x >> 5;
        sz_[w] = z; s1_[w] = e1; s2_[w] = e2; s3_[w] = e3;
    }
    __syncthreads();
    if (threadIdx.x == 0) {
        double Z = 0.0, t1 = 0.0, t2 = 0.0, t3 = 0.0;
#pragma unroll
        for (int w = 0; w < 8; w++) {
            Z += sz_[w]; t1 += s1_[w]; t2 += s2_[w]; t3 += s3_[w];
        }
        Z -= (double)n;  // remove diagonal (each contributes exactly 1)
        // loss = sum p*log(1+d2) + log(Z)*sum(p) + sum p*log(p)
        out[0] = (float)(t1 + log(Z) * t2 + t3);
    }
}

// ---------------- launch ------------------------------------------------------
extern "C" void kernel_launch(void* const* d_in, const int* in_sizes, int n_in,
                              void* d_out, int out_size) {
    const float2* emb   = (const float2*)d_in[0];
    const float*  p     = (const float*)d_in[1];
    const int*    heads = (const int*)d_in[2];
    const int*    tails = (const int*)d_in[3];
    int n = in_sizes[0] / 2;
    int E = in_sizes[1];

    k_fused<<<NTOTAL_BLOCKS, THREADS>>>(emb, p, heads, tails, E);
    k_final<<<1, 256>>>((float*)d_out, n);
}